// round 14
// baseline (speedup 1.0000x reference)
#include <cuda_runtime.h>
#include <cuda_bf16.h>
#include <cuda_fp16.h>
#include <math.h>
#include <float.h>
#include <stdint.h>

// Problem constants (fixed by the dataset)
#define NROWS 16384   // B*K = 256*64
#define D_IN  256
#define DB    512
#define NC    1024
#define KTOP  8
#define KSEL  12      // refine candidates
#define TEMP  0.1f

// ---------------- scratch (static device globals; no allocation) -------------
__device__ __align__(1024) __nv_bfloat16 g_as[(size_t)NROWS * 768];   // [hi|mid|lo]
__device__ __align__(1024) __nv_bfloat16 g_wb[(size_t)DB * 768];      // [hi|mid|lo]
__device__ __align__(1024) __nv_bfloat16 g_zs[(size_t)NROWS * 512];   // z_hi
__device__ __align__(1024) __nv_bfloat16 g_eb[(size_t)NC * 512];      // e_hi
__device__ __align__(1024) float  g_z[(size_t)NROWS * DB];   // fp32 z
__device__ __align__(1024) __half g_Dk[(size_t)NROWS * NC];  // fp16 selection keys
__device__ __align__(1024) uint2  g_sel[(size_t)NROWS * KTOP]; // (w bits, idx)
__device__ float g_enorm[NC];
__device__ float g_usage[NC];
__device__ float g_vq;

// ---------------- helpers -----------------------------------------------------
__device__ __forceinline__ void cp16(void* dst, const void* src) {
    uint32_t d = (uint32_t)__cvta_generic_to_shared(dst);
    asm volatile("cp.async.cg.shared.global [%0], [%1], 16;" :: "r"(d), "l"(src));
}
__device__ __forceinline__ void cp_commit() {
    asm volatile("cp.async.commit_group;" ::: "memory");
}
__device__ __forceinline__ void split3(float v, __nv_bfloat16& hi, __nv_bfloat16& mid,
                                       __nv_bfloat16& lo) {
    hi = __float2bfloat16(v);
    float r1 = v - __bfloat162float(hi);
    mid = __float2bfloat16(r1);
    lo = __float2bfloat16(r1 - __bfloat162float(mid));
}
__device__ __forceinline__ void mma16816(float* c, const uint32_t* a,
                                         uint32_t b0, uint32_t b1) {
    asm volatile(
        "mma.sync.aligned.m16n8k16.row.col.f32.bf16.bf16.f32 "
        "{%0,%1,%2,%3}, {%4,%5,%6,%7}, {%8,%9}, {%0,%1,%2,%3};"
        : "+f"(c[0]), "+f"(c[1]), "+f"(c[2]), "+f"(c[3])
        : "r"(a[0]), "r"(a[1]), "r"(a[2]), "r"(a[3]), "r"(b0), "r"(b1));
}
__device__ __forceinline__ void ldsm4(uint32_t* r, uint32_t addr) {
    asm volatile("ldmatrix.sync.aligned.m8n8.x4.shared.b16 {%0,%1,%2,%3}, [%4];"
        : "=r"(r[0]), "=r"(r[1]), "=r"(r[2]), "=r"(r[3]) : "r"(addr));
}
// monotone u16 map of an fp16 bit pattern (order-preserving total order)
__device__ __forceinline__ uint32_t h2key(uint32_t h16) {
    uint32_t neg = h16 >> 15;
    return h16 ^ (0x8000u | (neg * 0x7FFFu));
}
__device__ __forceinline__ uint32_t key2h(uint32_t k16) {
    uint32_t pos = k16 >> 15;
    return k16 ^ (pos ? 0x8000u : 0xFFFFu);
}

// ---------------- pre-kernels: splits + norms ---------------------------------
__global__ void split_slots_kernel(const float* __restrict__ slots) {
    int idx = blockIdx.x * 256 + threadIdx.x;
    int row = idx >> 8, k = idx & 255;
    __nv_bfloat16 hi, mid, lo;
    split3(slots[idx], hi, mid, lo);
    __nv_bfloat16* dst = g_as + (size_t)row * 768;
    dst[k] = hi;  dst[256 + k] = mid;  dst[512 + k] = lo;
}

__global__ void split_w_kernel(const float* __restrict__ W) {
    int idx = blockIdx.x * 256 + threadIdx.x;
    int k = idx >> 9, n = idx & 511;
    __nv_bfloat16 hi, mid, lo;
    split3(W[idx], hi, mid, lo);
    __nv_bfloat16* dst = g_wb + (size_t)n * 768;
    dst[k] = hi;  dst[256 + k] = mid;  dst[512 + k] = lo;
}

__global__ void init_kernel(const float* __restrict__ embed) {
    int w = threadIdx.x >> 5, lane = threadIdx.x & 31;
    int code = blockIdx.x * 8 + w;
    if (code < NC) {
        const float* e = embed + (size_t)code * DB;
        __nv_bfloat16* dst = g_eb + (size_t)code * 512;
        float s = 0.f;
        #pragma unroll
        for (int i = lane; i < DB; i += 32) {
            float v = e[i];
            s += v * v;
            dst[i] = __float2bfloat16(v);
        }
        #pragma unroll
        for (int o = 16; o; o >>= 1) s += __shfl_down_sync(0xffffffffu, s, o);
        if (lane == 0) g_enorm[code] = s;
    }
    if (blockIdx.x == 0) {
        for (int i = threadIdx.x; i < NC; i += blockDim.x) g_usage[i] = 0.f;
        if (threadIdx.x == 0) g_vq = 0.f;
    }
}

// ---------------- bf16 mma.sync GEMM: C[M,N] = A[M,K'] * B[N,K']^T --------------
// Block 128x256, 16 warps (4m x 4n), warp tile 32x64, K-chunk 32, double buffer.
// 512 threads: 4 warps/SMSP for latency hiding (same tile => same L2 reuse).
// EPI=1: 6-term split GEMM via nibble-mapped chunk offsets; +bias; fp32 C + z_hi.
// EPI=2: linear K; write fp16 key = enorm[col] - 2*acc - 170 (row-term dropped).
#define SM_PITCH 40
#define A_BYTES  (128 * SM_PITCH * 2)
#define B_BYTES  (256 * SM_PITCH * 2)
#define STAGE    (A_BYTES + B_BYTES)
#define GEMM_SMEM (2 * STAGE)

template<int KCH, int EPI>
__global__ void __launch_bounds__(512)
tc_gemm(const __nv_bfloat16* __restrict__ A, int lda,
        const __nv_bfloat16* __restrict__ B, int ldb,
        const float* __restrict__ bias,
        float* __restrict__ C, int ldc,
        __nv_bfloat16* __restrict__ Csplit) {
    extern __shared__ __align__(128) char smem[];
    const uint32_t sbase = (uint32_t)__cvta_generic_to_shared(smem);
    const int tid  = threadIdx.x;
    const int wid  = tid >> 5;
    const int lane = tid & 31;
    const int g    = lane >> 2;
    const int t    = lane & 3;
    const int wm   = wid & 3;        // 0..3 (M: 4 x 32)
    const int wn   = wid >> 2;       // 0..3 (N: 4 x 64)
    const int row0 = blockIdx.y * 128;
    const int col0 = blockIdx.x * 256;
    const int r8   = lane & 7;
    const int sub  = lane >> 3;

    float acc[2][8][4];
    #pragma unroll
    for (int mi = 0; mi < 2; mi++)
        #pragma unroll
        for (int nj = 0; nj < 8; nj++)
            #pragma unroll
            for (int q = 0; q < 4; q++) acc[mi][nj][q] = 0.f;

    auto do_copy = [&](int c, int s) {
        char* sA = smem + s * STAGE;
        char* sB = sA + A_BYTES;
        int ak, bk;
        if (EPI == 1) {
            int term = c >> 3, j = c & 7;
            ak = (int)((0x210100u >> (term * 4)) & 15u) * 256 + j * 32;
            bk = (int)((0x012010u >> (term * 4)) & 15u) * 256 + j * 32;
        } else {
            ak = c * 32; bk = c * 32;
        }
        #pragma unroll
        for (int i = 0; i < 3; i++) {
            int tt = tid + 512 * i;
            if (tt < 512) {                       // A: 128 rows x 4 x 16B
                int r = tt >> 2, kc = tt & 3;
                cp16(sA + r * (SM_PITCH * 2) + kc * 16,
                     A + (size_t)(row0 + r) * lda + ak + kc * 8);
            } else {                              // B: 256 rows x 4 x 16B
                int u = tt - 512;
                int r = u >> 2, kc = u & 3;
                cp16(sB + r * (SM_PITCH * 2) + kc * 16,
                     B + (size_t)(col0 + r) * ldb + bk + kc * 8);
            }
        }
        cp_commit();
    };

    do_copy(0, 0);
    for (int c = 0; c < KCH; c++) {
        const int s = c & 1;
        if (c + 1 < KCH) {
            do_copy(c + 1, s ^ 1);
            asm volatile("cp.async.wait_group 1;" ::: "memory");
        } else {
            asm volatile("cp.async.wait_group 0;" ::: "memory");
        }
        __syncthreads();

        const uint32_t sAu = sbase + s * STAGE;
        const uint32_t sBu = sAu + A_BYTES;
        #pragma unroll
        for (int k16 = 0; k16 < 2; k16++) {
            uint32_t af[2][4];
            {
                int arow = wm * 32 + (sub & 1) * 8 + r8;
                int akc  = k16 * 16 + (sub >> 1) * 8;
                #pragma unroll
                for (int mi = 0; mi < 2; mi++)
                    ldsm4(af[mi], sAu + ((arow + mi * 16) * SM_PITCH + akc) * 2);
            }
            uint32_t bf[4][4];
            {
                int bn  = wn * 64 + (sub >> 1) * 8 + r8;
                int bkc = k16 * 16 + (sub & 1) * 8;
                #pragma unroll
                for (int nj2 = 0; nj2 < 4; nj2++)
                    ldsm4(bf[nj2], sBu + ((bn + nj2 * 16) * SM_PITCH + bkc) * 2);
            }
            #pragma unroll
            for (int nj2 = 0; nj2 < 4; nj2++) {
                #pragma unroll
                for (int mi = 0; mi < 2; mi++) {
                    mma16816(acc[mi][2 * nj2],     af[mi], bf[nj2][0], bf[nj2][1]);
                    mma16816(acc[mi][2 * nj2 + 1], af[mi], bf[nj2][2], bf[nj2][3]);
                }
            }
        }
        __syncthreads();
    }

    if (EPI == 2) {
        __half* Ck = (__half*)C;
        float en0[8], en1[8];
        #pragma unroll
        for (int nj = 0; nj < 8; nj++) {
            int col = col0 + wn * 64 + nj * 8 + t * 2;
            en0[nj] = g_enorm[col] - 170.f;
            en1[nj] = g_enorm[col + 1] - 170.f;
        }
        #pragma unroll
        for (int mi = 0; mi < 2; mi++) {
            #pragma unroll
            for (int nj = 0; nj < 8; nj++) {
                const float* cr = acc[mi][nj];
                int row = row0 + wm * 32 + mi * 16 + g;
                int col = col0 + wn * 64 + nj * 8 + t * 2;
                *(__half2*)(Ck + (size_t)row * ldc + col) =
                    __floats2half2_rn(en0[nj] - 2.f * cr[0], en1[nj] - 2.f * cr[1]);
                *(__half2*)(Ck + (size_t)(row + 8) * ldc + col) =
                    __floats2half2_rn(en0[nj] - 2.f * cr[2], en1[nj] - 2.f * cr[3]);
            }
        }
    } else {
        #pragma unroll
        for (int mi = 0; mi < 2; mi++) {
            #pragma unroll
            for (int nj = 0; nj < 8; nj++) {
                const float* cr = acc[mi][nj];
                int row = row0 + wm * 32 + mi * 16 + g;
                int col = col0 + wn * 64 + nj * 8 + t * 2;
                float bx = bias[col], by = bias[col + 1];
                float v0 = cr[0] + bx, v1 = cr[1] + by;
                float v2 = cr[2] + bx, v3 = cr[3] + by;
                *(float2*)(C + (size_t)row * ldc + col)       = make_float2(v0, v1);
                *(float2*)(C + (size_t)(row + 8) * ldc + col) = make_float2(v2, v3);
                __nv_bfloat162 hp0 = {__float2bfloat16(v0), __float2bfloat16(v1)};
                __nv_bfloat162 hp1 = {__float2bfloat16(v2), __float2bfloat16(v3)};
                *(__nv_bfloat162*)(Csplit + (size_t)row * 512 + col)       = hp0;
                *(__nv_bfloat162*)(Csplit + (size_t)(row + 8) * 512 + col) = hp1;
            }
        }
    }
}

// ---------------- kernel A: select -> exact refine -> sort -> weights ----------
__global__ void __launch_bounds__(256)
select_kernel(const float* __restrict__ embed, float* __restrict__ out) {
    int w = threadIdx.x >> 5, lane = threadIdx.x & 31;
    int r = blockIdx.x * 8 + w;

    const float4* zr4 = (const float4*)(g_z + (size_t)r * DB);
    float4 zreg[4];
    float zn = 0.f;
    #pragma unroll
    for (int i = 0; i < 4; i++) {
        float4 v = zr4[lane + 32 * i];
        zreg[i] = v;
        zn += v.x * v.x + v.y * v.y + v.z * v.z + v.w * v.w;
    }
    #pragma unroll
    for (int o = 16; o; o >>= 1) zn += __shfl_xor_sync(0xffffffffu, zn, o);

    // pass 1: per-lane min via hmin2 tree
    const uint4* Dr = (const uint4*)(g_Dk + (size_t)r * NC);
    uint4 kv[4];
    #pragma unroll
    for (int it = 0; it < 4; it++) kv[it] = Dr[lane + 32 * it];

    __half2 m2 = *reinterpret_cast<__half2*>(&kv[0].x);
    #pragma unroll
    for (int it = 0; it < 4; it++) {
        __half2 a = *reinterpret_cast<__half2*>(&kv[it].x);
        __half2 b = *reinterpret_cast<__half2*>(&kv[it].y);
        __half2 c = *reinterpret_cast<__half2*>(&kv[it].z);
        __half2 d = *reinterpret_cast<__half2*>(&kv[it].w);
        m2 = __hmin2(m2, __hmin2(__hmin2(a, b), __hmin2(c, d)));
    }
    __half mv = __hmin(__low2half(m2), __high2half(m2));
    uint32_t laneKey = (h2key((uint32_t)__half_as_ushort(mv)) << 5) | (uint32_t)lane;

    // threshold T16 = u16-key of 12th smallest lane-min
    uint32_t m = laneKey, T = 0;
    #pragma unroll
    for (int j = 0; j < KSEL; j++) {
        uint32_t best = m;
        #pragma unroll
        for (int o = 16; o; o >>= 1)
            best = min(best, __shfl_xor_sync(0xffffffffu, best, o));
        T = best;
        if (m == best) m = 0xFFFFFFFFu;
    }
    const uint32_t T16 = T >> 5;
    const uint32_t Tfull = (T16 << 10) | 1023u;
    const __half Th = __ushort_as_half((unsigned short)key2h(T16));

    // pass 2: group-filtered collect
    uint32_t td[KSEL];
    #pragma unroll
    for (int j = 0; j < KSEL; j++) td[j] = 0xFFFFFFFFu;

    auto insert = [&](uint32_t key) {
        if (key <= Tfull && key < td[KSEL - 1]) {
            #pragma unroll
            for (int j = KSEL - 1; j >= 0; j--) {
                bool shift = (j > 0) && (td[j - 1] > key);
                if (shift) td[j] = td[j - 1];
                else       { td[j] = key; break; }
            }
        }
    };

    #pragma unroll
    for (int it = 0; it < 4; it++) {
        __half2 a = *reinterpret_cast<__half2*>(&kv[it].x);
        __half2 b = *reinterpret_cast<__half2*>(&kv[it].y);
        __half2 c = *reinterpret_cast<__half2*>(&kv[it].z);
        __half2 d = *reinterpret_cast<__half2*>(&kv[it].w);
        __half2 gm2 = __hmin2(__hmin2(a, b), __hmin2(c, d));
        __half gm = __hmin(__low2half(gm2), __high2half(gm2));
        if (__hle(gm, Th)) {
            uint32_t c0 = (uint32_t)(lane + 32 * it) * 8;
            insert((h2key(kv[it].x & 0xFFFFu) << 10) | (c0 + 0));
            insert((h2key(kv[it].x >> 16)     << 10) | (c0 + 1));
            insert((h2key(kv[it].y & 0xFFFFu) << 10) | (c0 + 2));
            insert((h2key(kv[it].y >> 16)     << 10) | (c0 + 3));
            insert((h2key(kv[it].z & 0xFFFFu) << 10) | (c0 + 4));
            insert((h2key(kv[it].z >> 16)     << 10) | (c0 + 5));
            insert((h2key(kv[it].w & 0xFFFFu) << 10) | (c0 + 6));
            insert((h2key(kv[it].w >> 16)     << 10) | (c0 + 7));
        }
    }

    // warp merge
    int ci[KSEL];
    int pos = 0;
    #pragma unroll
    for (int j = 0; j < KSEL; j++) {
        uint32_t cur = (pos < KSEL) ? td[pos] : 0xFFFFFFFFu;
        uint32_t best = cur;
        #pragma unroll
        for (int o = 16; o; o >>= 1)
            best = min(best, __shfl_xor_sync(0xffffffffu, best, o));
        ci[j] = (int)(best & 1023u);
        if (cur == best) pos++;
    }

    // exact fp32 refine
    float dot[KSEL];
    #pragma unroll
    for (int j = 0; j < KSEL; j++) dot[j] = 0.f;
    #pragma unroll
    for (int i = 0; i < 4; i++) {
        int c4 = lane + 32 * i;
        float4 zv = zreg[i];
        #pragma unroll
        for (int j = 0; j < KSEL; j++) {
            float4 f = ((const float4*)(embed + (size_t)ci[j] * DB))[c4];
            dot[j] += zv.x * f.x + zv.y * f.y + zv.z * f.z + zv.w * f.w;
        }
    }
    #pragma unroll
    for (int o = 16; o; o >>= 1) {
        #pragma unroll
        for (int j = 0; j < KSEL; j++)
            dot[j] += __shfl_xor_sync(0xffffffffu, dot[j], o);
    }
    float xd[KSEL];
    #pragma unroll
    for (int j = 0; j < KSEL; j++) xd[j] = zn + g_enorm[ci[j]] - 2.f * dot[j];

    // bubble sort (all lanes identical; tie -> smaller index)
    #pragma unroll
    for (int a = 0; a < KSEL - 1; a++) {
        #pragma unroll
        for (int b = 0; b < KSEL - 1 - a; b++) {
            bool sw = (xd[b + 1] < xd[b]) ||
                      (xd[b + 1] == xd[b] && ci[b + 1] < ci[b]);
            if (sw) {
                float tf = xd[b]; xd[b] = xd[b + 1]; xd[b + 1] = tf;
                int   tn = ci[b]; ci[b] = ci[b + 1]; ci[b + 1] = tn;
            }
        }
    }

    // softmax over exact sqrt(d2) of top-8
    float wj[KTOP];
    float vmin = sqrtf(fmaxf(xd[0], 0.f));
    float wsum = 0.f;
    #pragma unroll
    for (int j = 0; j < KTOP; j++) {
        float v = sqrtf(fmaxf(xd[j], 0.f));
        wj[j] = expf(-(v - vmin) / TEMP);
        wsum += wj[j];
    }
    float inv = 1.f / wsum;
    #pragma unroll
    for (int j = 0; j < KTOP; j++) wj[j] *= inv;

    // lane j<8 emits (w_j, idx_j); usage atomics; top-1 index
    float wv = wj[0]; int iv = ci[0];
    #pragma unroll
    for (int j = 1; j < KTOP; j++) {
        if (lane == j) { wv = wj[j]; iv = ci[j]; }
    }
    if (lane < KTOP) {
        g_sel[(size_t)r * KTOP + lane] = make_uint2(__float_as_uint(wv), (uint32_t)iv);
        atomicAdd(&g_usage[iv], wv);
    }
    if (lane == 0) out[(size_t)NROWS * DB + r] = (float)ci[0];
}

// ---------------- kernel B: q gather + vq --------------------------------------
__global__ void __launch_bounds__(256)
gather_kernel(const float* __restrict__ embed, float* __restrict__ out) {
    int w = threadIdx.x >> 5, lane = threadIdx.x & 31;
    int r = blockIdx.x * 8 + w;

    uint2 p = make_uint2(0, 0);
    if (lane < KTOP) p = g_sel[(size_t)r * KTOP + lane];
    float wv = __uint_as_float(p.x);
    int   iv = (int)p.y;

    float w8[KTOP]; int i8[KTOP];
    #pragma unroll
    for (int j = 0; j < KTOP; j++) {
        w8[j] = __shfl_sync(0xffffffffu, wv, j);
        i8[j] = __shfl_sync(0xffffffffu, iv, j);
    }

    const float4* zr4 = (const float4*)(g_z + (size_t)r * DB);
    float vql = 0.f;
    #pragma unroll
    for (int i = 0; i < 4; i++) {
        int c4 = lane + 32 * i;
        float4 a = make_float4(0.f, 0.f, 0.f, 0.f);
        #pragma unroll
        for (int j = 0; j < KTOP; j++) {
            float4 f = ((const float4*)(embed + (size_t)i8[j] * DB))[c4];
            a.x += w8[j] * f.x; a.y += w8[j] * f.y;
            a.z += w8[j] * f.z; a.w += w8[j] * f.w;
        }
        ((float4*)(out + (size_t)r * DB))[c4] = a;
        float4 zv = zr4[c4];
        float dx = zv.x - a.x, dy = zv.y - a.y;
        float dz = zv.z - a.z, dw = zv.w - a.w;
        vql += dx * dx + dy * dy + dz * dz + dw * dw;
    }
    #pragma unroll
    for (int o = 16; o; o >>= 1) vql += __shfl_down_sync(0xffffffffu, vql, o);
    if (lane == 0) atomicAdd(&g_vq, vql);
}

// ---------------- finalize scalars --------------------------------------------
__global__ void finalize_kernel(float* __restrict__ out) {
    __shared__ float sh[256];
    float s = 0.f;
    for (int c = threadIdx.x; c < NC; c += 256) {
        float u = g_usage[c] * (1.f / (float)NROWS);
        s += u * logf(u + 1e-8f);
    }
    sh[threadIdx.x] = s;
    __syncthreads();
    for (int o = 128; o; o >>= 1) {
        if (threadIdx.x < o) sh[threadIdx.x] += sh[threadIdx.x + o];
        __syncthreads();
    }
    if (threadIdx.x == 0) {
        size_t base = (size_t)NROWS * DB + NROWS;
        out[base + 0] = g_vq * (1.f / (float)((size_t)NROWS * DB));
        out[base + 1] = -sh[0];
    }
}

// ---------------- launch --------------------------------------------------------
extern "C" void kernel_launch(void* const* d_in, const int* in_sizes, int n_in,
                              void* d_out, int out_size) {
    const float* slots = (const float*)d_in[0];
    const float* W     = (const float*)d_in[1];
    const float* bias  = (const float*)d_in[2];
    const float* embed = (const float*)d_in[3];
    float* out = (float*)d_out;

    float* zp = nullptr;
    __half* dkp = nullptr;
    __nv_bfloat16 *asp = nullptr, *wbp = nullptr, *zsp = nullptr, *ebp = nullptr;
    cudaGetSymbolAddress((void**)&zp,  g_z);
    cudaGetSymbolAddress((void**)&dkp, g_Dk);
    cudaGetSymbolAddress((void**)&asp, g_as);
    cudaGetSymbolAddress((void**)&wbp, g_wb);
    cudaGetSymbolAddress((void**)&zsp, g_zs);
    cudaGetSymbolAddress((void**)&ebp, g_eb);

    cudaFuncSetAttribute(tc_gemm<48, 1>,
                         cudaFuncAttributeMaxDynamicSharedMemorySize, GEMM_SMEM);
    cudaFuncSetAttribute(tc_gemm<16, 2>,
                         cudaFuncAttributeMaxDynamicSharedMemorySize, GEMM_SMEM);

    split_slots_kernel<<<(NROWS * D_IN) / 256, 256>>>(slots);
    split_w_kernel<<<(D_IN * DB) / 256, 256>>>(W);
    init_kernel<<<128, 256>>>(embed);

    // z = slots @ W + b : 6-term mapped split over [hi|mid|lo] -> fp32 z + bf16 z_hi
    tc_gemm<48, 1><<<dim3(2, 128), 512, GEMM_SMEM>>>(
        asp, 768, wbp, 768, bias, zp, 512, zsp);

    // fp16 selection keys = enorm - 2*(z_hi . e_hi) - 170 : K = 512
    tc_gemm<16, 2><<<dim3(4, 128), 512, GEMM_SMEM>>>(
        zsp, 512, ebp, 512, nullptr, (float*)dkp, 1024, nullptr);

    select_kernel<<<NROWS / 8, 256>>>(embed, out);
    gather_kernel<<<NROWS / 8, 256>>>(embed, out);
    finalize_kernel<<<1, 256>>>(out);
}

// round 15
// speedup vs baseline: 1.0627x; 1.0627x over previous
#include <cuda_runtime.h>
#include <cuda_bf16.h>
#include <cuda_fp16.h>
#include <math.h>
#include <float.h>
#include <stdint.h>

// Problem constants (fixed by the dataset)
#define NROWS 16384   // B*K = 256*64
#define D_IN  256
#define DB    512
#define NC    1024
#define KTOP  8
#define KSEL  12      // refine candidates
#define TEMP  0.1f

// ---------------- scratch (static device globals; no allocation) -------------
__device__ __align__(1024) __nv_bfloat16 g_as[(size_t)NROWS * 768];   // [hi|mid|lo]
__device__ __align__(1024) __nv_bfloat16 g_wb[(size_t)DB * 768];      // [hi|mid|lo]
__device__ __align__(1024) __nv_bfloat16 g_zs[(size_t)NROWS * 512];   // z_hi
__device__ __align__(1024) __nv_bfloat16 g_eb[(size_t)NC * 512];      // e_hi
__device__ __align__(1024) float  g_z[(size_t)NROWS * DB];   // fp32 z
__device__ __align__(1024) __half g_Dk[(size_t)NROWS * NC];  // fp16 selection keys
__device__ __align__(1024) uint2  g_sel[(size_t)NROWS * KTOP]; // (w bits, idx)
__device__ float g_enorm[NC];
__device__ float g_usage[NC];
__device__ float g_vq;

// ---------------- helpers -----------------------------------------------------
__device__ __forceinline__ void cp16(void* dst, const void* src) {
    uint32_t d = (uint32_t)__cvta_generic_to_shared(dst);
    asm volatile("cp.async.cg.shared.global [%0], [%1], 16;" :: "r"(d), "l"(src));
}
__device__ __forceinline__ void cp_commit() {
    asm volatile("cp.async.commit_group;" ::: "memory");
}
__device__ __forceinline__ void split3(float v, __nv_bfloat16& hi, __nv_bfloat16& mid,
                                       __nv_bfloat16& lo) {
    hi = __float2bfloat16(v);
    float r1 = v - __bfloat162float(hi);
    mid = __float2bfloat16(r1);
    lo = __float2bfloat16(r1 - __bfloat162float(mid));
}
__device__ __forceinline__ void mma16816(float* c, const uint32_t* a,
                                         uint32_t b0, uint32_t b1) {
    asm volatile(
        "mma.sync.aligned.m16n8k16.row.col.f32.bf16.bf16.f32 "
        "{%0,%1,%2,%3}, {%4,%5,%6,%7}, {%8,%9}, {%0,%1,%2,%3};"
        : "+f"(c[0]), "+f"(c[1]), "+f"(c[2]), "+f"(c[3])
        : "r"(a[0]), "r"(a[1]), "r"(a[2]), "r"(a[3]), "r"(b0), "r"(b1));
}
__device__ __forceinline__ void ldsm4(uint32_t* r, uint32_t addr) {
    asm volatile("ldmatrix.sync.aligned.m8n8.x4.shared.b16 {%0,%1,%2,%3}, [%4];"
        : "=r"(r[0]), "=r"(r[1]), "=r"(r[2]), "=r"(r[3]) : "r"(addr));
}
// monotone u16 map of an fp16 bit pattern (order-preserving total order)
__device__ __forceinline__ uint32_t h2key(uint32_t h16) {
    uint32_t neg = h16 >> 15;
    return h16 ^ (0x8000u | (neg * 0x7FFFu));
}
__device__ __forceinline__ uint32_t key2h(uint32_t k16) {
    uint32_t pos = k16 >> 15;
    return k16 ^ (pos ? 0x8000u : 0xFFFFu);
}

// ---------------- pre-kernels: splits + norms ---------------------------------
__global__ void split_slots_kernel(const float* __restrict__ slots) {
    int idx = blockIdx.x * 256 + threadIdx.x;
    int row = idx >> 8, k = idx & 255;
    __nv_bfloat16 hi, mid, lo;
    split3(slots[idx], hi, mid, lo);
    __nv_bfloat16* dst = g_as + (size_t)row * 768;
    dst[k] = hi;  dst[256 + k] = mid;  dst[512 + k] = lo;
}

__global__ void split_w_kernel(const float* __restrict__ W) {
    int idx = blockIdx.x * 256 + threadIdx.x;
    int k = idx >> 9, n = idx & 511;
    __nv_bfloat16 hi, mid, lo;
    split3(W[idx], hi, mid, lo);
    __nv_bfloat16* dst = g_wb + (size_t)n * 768;
    dst[k] = hi;  dst[256 + k] = mid;  dst[512 + k] = lo;
}

__global__ void init_kernel(const float* __restrict__ embed) {
    int w = threadIdx.x >> 5, lane = threadIdx.x & 31;
    int code = blockIdx.x * 8 + w;
    if (code < NC) {
        const float* e = embed + (size_t)code * DB;
        __nv_bfloat16* dst = g_eb + (size_t)code * 512;
        float s = 0.f;
        #pragma unroll
        for (int i = lane; i < DB; i += 32) {
            float v = e[i];
            s += v * v;
            dst[i] = __float2bfloat16(v);
        }
        #pragma unroll
        for (int o = 16; o; o >>= 1) s += __shfl_down_sync(0xffffffffu, s, o);
        if (lane == 0) g_enorm[code] = s;
    }
    if (blockIdx.x == 0) {
        for (int i = threadIdx.x; i < NC; i += blockDim.x) g_usage[i] = 0.f;
        if (threadIdx.x == 0) g_vq = 0.f;
    }
}

// ---------------- bf16 mma.sync GEMM: C[M,N] = A[M,K'] * B[N,K']^T --------------
// Block 128x256, 8 warps (2m x 4n), warp tile 64x64, K-chunk 32.
// 3-stage cp.async pipeline, ONE __syncthreads per chunk.
// EPI=1: 6-term split GEMM via nibble-mapped chunk offsets; +bias; fp32 C + z_hi.
// EPI=2: linear K; write fp16 key = enorm[col] - 2*acc - 170 (row-term dropped).
#define SM_PITCH 40
#define A_BYTES  (128 * SM_PITCH * 2)
#define B_BYTES  (256 * SM_PITCH * 2)
#define STAGE    (A_BYTES + B_BYTES)
#define NSTAGE   3
#define GEMM_SMEM (NSTAGE * STAGE)       // 92160

template<int KCH, int EPI>
__global__ void __launch_bounds__(256)
tc_gemm(const __nv_bfloat16* __restrict__ A, int lda,
        const __nv_bfloat16* __restrict__ B, int ldb,
        const float* __restrict__ bias,
        float* __restrict__ C, int ldc,
        __nv_bfloat16* __restrict__ Csplit) {
    extern __shared__ __align__(128) char smem[];
    const uint32_t sbase = (uint32_t)__cvta_generic_to_shared(smem);
    const int tid  = threadIdx.x;
    const int wid  = tid >> 5;
    const int lane = tid & 31;
    const int g    = lane >> 2;
    const int t    = lane & 3;
    const int wm   = wid & 1;
    const int wn   = wid >> 1;
    const int row0 = blockIdx.y * 128;
    const int col0 = blockIdx.x * 256;
    const int r8   = lane & 7;
    const int sub  = lane >> 3;

    float acc[4][8][4];
    #pragma unroll
    for (int mi = 0; mi < 4; mi++)
        #pragma unroll
        for (int nj = 0; nj < 8; nj++)
            #pragma unroll
            for (int q = 0; q < 4; q++) acc[mi][nj][q] = 0.f;

    auto do_copy = [&](int c, int s) {
        char* sA = smem + s * STAGE;
        char* sB = sA + A_BYTES;
        int ak, bk;
        if (EPI == 1) {
            int term = c >> 3, j = c & 7;
            ak = (int)((0x210100u >> (term * 4)) & 15u) * 256 + j * 32;
            bk = (int)((0x012010u >> (term * 4)) & 15u) * 256 + j * 32;
        } else {
            ak = c * 32; bk = c * 32;
        }
        #pragma unroll
        for (int i = 0; i < 6; i++) {
            int tt = tid + 256 * i;
            if (tt < 512) {
                int r = tt >> 2, kc = tt & 3;
                cp16(sA + r * (SM_PITCH * 2) + kc * 16,
                     A + (size_t)(row0 + r) * lda + ak + kc * 8);
            } else {
                int u = tt - 512;
                int r = u >> 2, kc = u & 3;
                cp16(sB + r * (SM_PITCH * 2) + kc * 16,
                     B + (size_t)(col0 + r) * ldb + bk + kc * 8);
            }
        }
        cp_commit();
    };

    do_copy(0, 0);
    do_copy(1, 1);
    for (int c = 0; c < KCH; c++) {
        const int s = c % NSTAGE;
        if (c + 1 < KCH) {
            asm volatile("cp.async.wait_group 1;" ::: "memory");
        } else {
            asm volatile("cp.async.wait_group 0;" ::: "memory");
        }
        __syncthreads();   // data(s) visible; compute(c-1) done -> stage (c+2)%3 free

        if (c + 2 < KCH) do_copy(c + 2, (c + 2) % NSTAGE);

        const uint32_t sAu = sbase + s * STAGE;
        const uint32_t sBu = sAu + A_BYTES;
        #pragma unroll
        for (int k16 = 0; k16 < 2; k16++) {
            uint32_t af[4][4];
            {
                int arow = wm * 64 + (sub & 1) * 8 + r8;
                int akc  = k16 * 16 + (sub >> 1) * 8;
                #pragma unroll
                for (int mi = 0; mi < 4; mi++)
                    ldsm4(af[mi], sAu + ((arow + mi * 16) * SM_PITCH + akc) * 2);
            }
            uint32_t bf[4][4];
            {
                int bn  = wn * 64 + (sub >> 1) * 8 + r8;
                int bkc = k16 * 16 + (sub & 1) * 8;
                #pragma unroll
                for (int nj2 = 0; nj2 < 4; nj2++)
                    ldsm4(bf[nj2], sBu + ((bn + nj2 * 16) * SM_PITCH + bkc) * 2);
            }
            #pragma unroll
            for (int nj2 = 0; nj2 < 4; nj2++) {
                #pragma unroll
                for (int mi = 0; mi < 4; mi++) {
                    mma16816(acc[mi][2 * nj2],     af[mi], bf[nj2][0], bf[nj2][1]);
                    mma16816(acc[mi][2 * nj2 + 1], af[mi], bf[nj2][2], bf[nj2][3]);
                }
            }
        }
    }

    if (EPI == 2) {
        __half* Ck = (__half*)C;
        float en0[8], en1[8];
        #pragma unroll
        for (int nj = 0; nj < 8; nj++) {
            int col = col0 + wn * 64 + nj * 8 + t * 2;
            en0[nj] = g_enorm[col] - 170.f;
            en1[nj] = g_enorm[col + 1] - 170.f;
        }
        #pragma unroll
        for (int mi = 0; mi < 4; mi++) {
            #pragma unroll
            for (int nj = 0; nj < 8; nj++) {
                const float* cr = acc[mi][nj];
                int row = row0 + wm * 64 + mi * 16 + g;
                int col = col0 + wn * 64 + nj * 8 + t * 2;
                *(__half2*)(Ck + (size_t)row * ldc + col) =
                    __floats2half2_rn(en0[nj] - 2.f * cr[0], en1[nj] - 2.f * cr[1]);
                *(__half2*)(Ck + (size_t)(row + 8) * ldc + col) =
                    __floats2half2_rn(en0[nj] - 2.f * cr[2], en1[nj] - 2.f * cr[3]);
            }
        }
    } else {
        #pragma unroll
        for (int mi = 0; mi < 4; mi++) {
            #pragma unroll
            for (int nj = 0; nj < 8; nj++) {
                const float* cr = acc[mi][nj];
                int row = row0 + wm * 64 + mi * 16 + g;
                int col = col0 + wn * 64 + nj * 8 + t * 2;
                float bx = bias[col], by = bias[col + 1];
                float v0 = cr[0] + bx, v1 = cr[1] + by;
                float v2 = cr[2] + bx, v3 = cr[3] + by;
                *(float2*)(C + (size_t)row * ldc + col)       = make_float2(v0, v1);
                *(float2*)(C + (size_t)(row + 8) * ldc + col) = make_float2(v2, v3);
                __nv_bfloat162 hp0 = {__float2bfloat16(v0), __float2bfloat16(v1)};
                __nv_bfloat162 hp1 = {__float2bfloat16(v2), __float2bfloat16(v3)};
                *(__nv_bfloat162*)(Csplit + (size_t)row * 512 + col)       = hp0;
                *(__nv_bfloat162*)(Csplit + (size_t)(row + 8) * 512 + col) = hp1;
            }
        }
    }
}

// ---------------- kernel A: select -> exact refine -> rank -> weights ----------
__global__ void __launch_bounds__(256)
select_kernel(const float* __restrict__ embed, float* __restrict__ out) {
    int w = threadIdx.x >> 5, lane = threadIdx.x & 31;
    int r = blockIdx.x * 8 + w;

    const float4* zr4 = (const float4*)(g_z + (size_t)r * DB);
    float4 zreg[4];
    float zn = 0.f;
    #pragma unroll
    for (int i = 0; i < 4; i++) {
        float4 v = zr4[lane + 32 * i];
        zreg[i] = v;
        zn += v.x * v.x + v.y * v.y + v.z * v.z + v.w * v.w;
    }
    #pragma unroll
    for (int o = 16; o; o >>= 1) zn += __shfl_xor_sync(0xffffffffu, zn, o);

    // pass 1: per-lane min via hmin2 tree
    const uint4* Dr = (const uint4*)(g_Dk + (size_t)r * NC);
    uint4 kv[4];
    #pragma unroll
    for (int it = 0; it < 4; it++) kv[it] = Dr[lane + 32 * it];

    __half2 m2 = *reinterpret_cast<__half2*>(&kv[0].x);
    #pragma unroll
    for (int it = 0; it < 4; it++) {
        __half2 a = *reinterpret_cast<__half2*>(&kv[it].x);
        __half2 b = *reinterpret_cast<__half2*>(&kv[it].y);
        __half2 c = *reinterpret_cast<__half2*>(&kv[it].z);
        __half2 d = *reinterpret_cast<__half2*>(&kv[it].w);
        m2 = __hmin2(m2, __hmin2(__hmin2(a, b), __hmin2(c, d)));
    }
    __half mv = __hmin(__low2half(m2), __high2half(m2));
    uint32_t laneKey = (h2key((uint32_t)__half_as_ushort(mv)) << 5) | (uint32_t)lane;

    // threshold T16 = u16-key of 12th smallest lane-min
    uint32_t m = laneKey, T = 0;
    #pragma unroll
    for (int j = 0; j < KSEL; j++) {
        uint32_t best = m;
        #pragma unroll
        for (int o = 16; o; o >>= 1)
            best = min(best, __shfl_xor_sync(0xffffffffu, best, o));
        T = best;
        if (m == best) m = 0xFFFFFFFFu;
    }
    const uint32_t T16 = T >> 5;
    const uint32_t Tfull = (T16 << 10) | 1023u;
    const __half Th = __ushort_as_half((unsigned short)key2h(T16));

    // pass 2: group-filtered collect
    uint32_t td[KSEL];
    #pragma unroll
    for (int j = 0; j < KSEL; j++) td[j] = 0xFFFFFFFFu;

    auto insert = [&](uint32_t key) {
        if (key <= Tfull && key < td[KSEL - 1]) {
            #pragma unroll
            for (int j = KSEL - 1; j >= 0; j--) {
                bool shift = (j > 0) && (td[j - 1] > key);
                if (shift) td[j] = td[j - 1];
                else       { td[j] = key; break; }
            }
        }
    };

    #pragma unroll
    for (int it = 0; it < 4; it++) {
        __half2 a = *reinterpret_cast<__half2*>(&kv[it].x);
        __half2 b = *reinterpret_cast<__half2*>(&kv[it].y);
        __half2 c = *reinterpret_cast<__half2*>(&kv[it].z);
        __half2 d = *reinterpret_cast<__half2*>(&kv[it].w);
        __half2 gm2 = __hmin2(__hmin2(a, b), __hmin2(c, d));
        __half gm = __hmin(__low2half(gm2), __high2half(gm2));
        if (__hle(gm, Th)) {
            uint32_t c0 = (uint32_t)(lane + 32 * it) * 8;
            insert((h2key(kv[it].x & 0xFFFFu) << 10) | (c0 + 0));
            insert((h2key(kv[it].x >> 16)     << 10) | (c0 + 1));
            insert((h2key(kv[it].y & 0xFFFFu) << 10) | (c0 + 2));
            insert((h2key(kv[it].y >> 16)     << 10) | (c0 + 3));
            insert((h2key(kv[it].z & 0xFFFFu) << 10) | (c0 + 4));
            insert((h2key(kv[it].z >> 16)     << 10) | (c0 + 5));
            insert((h2key(kv[it].w & 0xFFFFu) << 10) | (c0 + 6));
            insert((h2key(kv[it].w >> 16)     << 10) | (c0 + 7));
        }
    }

    // warp merge
    int ci[KSEL];
    int pos = 0;
    #pragma unroll
    for (int j = 0; j < KSEL; j++) {
        uint32_t cur = (pos < KSEL) ? td[pos] : 0xFFFFFFFFu;
        uint32_t best = cur;
        #pragma unroll
        for (int o = 16; o; o >>= 1)
            best = min(best, __shfl_xor_sync(0xffffffffu, best, o));
        ci[j] = (int)(best & 1023u);
        if (cur == best) pos++;
    }

    // exact fp32 refine
    float dot[KSEL];
    #pragma unroll
    for (int j = 0; j < KSEL; j++) dot[j] = 0.f;
    #pragma unroll
    for (int i = 0; i < 4; i++) {
        int c4 = lane + 32 * i;
        float4 zv = zreg[i];
        #pragma unroll
        for (int j = 0; j < KSEL; j++) {
            float4 f = ((const float4*)(embed + (size_t)ci[j] * DB))[c4];
            dot[j] += zv.x * f.x + zv.y * f.y + zv.z * f.z + zv.w * f.w;
        }
    }
    #pragma unroll
    for (int o = 16; o; o >>= 1) {
        #pragma unroll
        for (int j = 0; j < KSEL; j++)
            dot[j] += __shfl_xor_sync(0xffffffffu, dot[j], o);
    }
    float xd[KSEL];
    #pragma unroll
    for (int j = 0; j < KSEL; j++) xd[j] = zn + g_enorm[ci[j]] - 2.f * dot[j];

    // rank-based order: lane j (<12) owns candidate j, computes its rank
    // (xd/ci identical on all lanes; tie -> smaller index)
    float myd = (lane < KSEL) ? xd[lane] : FLT_MAX;
    int   myi = (lane < KSEL) ? ci[lane] : 0x7fffffff;
    int rank = 0;
    #pragma unroll
    for (int j = 0; j < KSEL; j++)
        rank += (xd[j] < myd) || (xd[j] == myd && ci[j] < myi);
    if (lane >= KSEL) rank = 31;

    // distributed softmax over rank<8: one sqrt+exp per lane
    uint32_t m0 = __ballot_sync(0xffffffffu, rank == 0);
    int src0 = __ffs(m0) - 1;
    float v  = sqrtf(fmaxf(myd, 0.f));
    float vmin = __shfl_sync(0xffffffffu, v, src0);
    float wj = (rank < KTOP) ? expf(-(v - vmin) / TEMP) : 0.f;
    float wsum = wj;
    #pragma unroll
    for (int o = 16; o; o >>= 1) wsum += __shfl_xor_sync(0xffffffffu, wsum, o);
    wj /= wsum;

    if (rank < KTOP) {
        g_sel[(size_t)r * KTOP + rank] = make_uint2(__float_as_uint(wj), (uint32_t)myi);
        atomicAdd(&g_usage[myi], wj);
        if (rank == 0) out[(size_t)NROWS * DB + r] = (float)myi;
    }
}

// ---------------- kernel B: q gather + vq --------------------------------------
__global__ void __launch_bounds__(256)
gather_kernel(const float* __restrict__ embed, float* __restrict__ out) {
    int w = threadIdx.x >> 5, lane = threadIdx.x & 31;
    int r = blockIdx.x * 8 + w;

    uint2 p = make_uint2(0, 0);
    if (lane < KTOP) p = g_sel[(size_t)r * KTOP + lane];
    float wv = __uint_as_float(p.x);
    int   iv = (int)p.y;

    float w8[KTOP]; int i8[KTOP];
    #pragma unroll
    for (int j = 0; j < KTOP; j++) {
        w8[j] = __shfl_sync(0xffffffffu, wv, j);
        i8[j] = __shfl_sync(0xffffffffu, iv, j);
    }

    const float4* zr4 = (const float4*)(g_z + (size_t)r * DB);
    float vql = 0.f;
    #pragma unroll
    for (int i = 0; i < 4; i++) {
        int c4 = lane + 32 * i;
        float4 a = make_float4(0.f, 0.f, 0.f, 0.f);
        #pragma unroll
        for (int j = 0; j < KTOP; j++) {
            float4 f = ((const float4*)(embed + (size_t)i8[j] * DB))[c4];
            a.x += w8[j] * f.x; a.y += w8[j] * f.y;
            a.z += w8[j] * f.z; a.w += w8[j] * f.w;
        }
        ((float4*)(out + (size_t)r * DB))[c4] = a;
        float4 zv = zr4[c4];
        float dx = zv.x - a.x, dy = zv.y - a.y;
        float dz = zv.z - a.z, dw = zv.w - a.w;
        vql += dx * dx + dy * dy + dz * dz + dw * dw;
    }
    #pragma unroll
    for (int o = 16; o; o >>= 1) vql += __shfl_down_sync(0xffffffffu, vql, o);
    if (lane == 0) atomicAdd(&g_vq, vql);
}

// ---------------- finalize scalars --------------------------------------------
__global__ void finalize_kernel(float* __restrict__ out) {
    __shared__ float sh[256];
    float s = 0.f;
    for (int c = threadIdx.x; c < NC; c += 256) {
        float u = g_usage[c] * (1.f / (float)NROWS);
        s += u * logf(u + 1e-8f);
    }
    sh[threadIdx.x] = s;
    __syncthreads();
    for (int o = 128; o; o >>= 1) {
        if (threadIdx.x < o) sh[threadIdx.x] += sh[threadIdx.x + o];
        __syncthreads();
    }
    if (threadIdx.x == 0) {
        size_t base = (size_t)NROWS * DB + NROWS;
        out[base + 0] = g_vq * (1.f / (float)((size_t)NROWS * DB));
        out[base + 1] = -sh[0];
    }
}

// ---------------- launch --------------------------------------------------------
extern "C" void kernel_launch(void* const* d_in, const int* in_sizes, int n_in,
                              void* d_out, int out_size) {
    const float* slots = (const float*)d_in[0];
    const float* W     = (const float*)d_in[1];
    const float* bias  = (const float*)d_in[2];
    const float* embed = (const float*)d_in[3];
    float* out = (float*)d_out;

    float* zp = nullptr;
    __half* dkp = nullptr;
    __nv_bfloat16 *asp = nullptr, *wbp = nullptr, *zsp = nullptr, *ebp = nullptr;
    cudaGetSymbolAddress((void**)&zp,  g_z);
    cudaGetSymbolAddress((void**)&dkp, g_Dk);
    cudaGetSymbolAddress((void**)&asp, g_as);
    cudaGetSymbolAddress((void**)&wbp, g_wb);
    cudaGetSymbolAddress((void**)&zsp, g_zs);
    cudaGetSymbolAddress((void**)&ebp, g_eb);

    cudaFuncSetAttribute(tc_gemm<48, 1>,
                         cudaFuncAttributeMaxDynamicSharedMemorySize, GEMM_SMEM);
    cudaFuncSetAttribute(tc_gemm<16, 2>,
                         cudaFuncAttributeMaxDynamicSharedMemorySize, GEMM_SMEM);

    split_slots_kernel<<<(NROWS * D_IN) / 256, 256>>>(slots);
    split_w_kernel<<<(D_IN * DB) / 256, 256>>>(W);
    init_kernel<<<128, 256>>>(embed);

    // z = slots @ W + b : 6-term mapped split over [hi|mid|lo] -> fp32 z + bf16 z_hi
    tc_gemm<48, 1><<<dim3(2, 128), 256, GEMM_SMEM>>>(
        asp, 768, wbp, 768, bias, zp, 512, zsp);

    // fp16 selection keys = enorm - 2*(z_hi . e_hi) - 170 : K = 512
    tc_gemm<16, 2><<<dim3(4, 128), 256, GEMM_SMEM>>>(
        zsp, 512, ebp, 512, nullptr, (float*)dkp, 1024, nullptr);

    select_kernel<<<NROWS / 8, 256>>>(embed, out);
    gather_kernel<<<NROWS / 8, 256>>>(embed, out);
    finalize_kernel<<<1, 256>>>(out);
}

// round 16
// speedup vs baseline: 1.2441x; 1.1706x over previous
#include <cuda_runtime.h>
#include <cuda_bf16.h>
#include <cuda_fp16.h>
#include <math.h>
#include <float.h>
#include <stdint.h>

// Problem constants (fixed by the dataset)
#define NROWS 16384   // B*K = 256*64
#define D_IN  256
#define DB    512
#define NC    1024
#define KTOP  8
#define KSEL  12      // refine candidates
#define TEMP  0.1f

// ---------------- scratch (static device globals; no allocation) -------------
// fp16 2-way split: products are EXACT in fp32 accum (11+11 mantissa bits < 24).
// GEMM1 (z = slots@W): 3 terms (hi.hi + hi.lo + lo.hi) -> K' = 768
// GEMM2 (keys): single term z_hi . e_hi, K = 512
__device__ __align__(1024) __half g_as[(size_t)NROWS * 512];   // [a_hi|a_lo]
__device__ __align__(1024) __half g_wb[(size_t)DB * 512];      // [w_hi|w_lo]
__device__ __align__(1024) __half g_zs[(size_t)NROWS * 512];   // z_hi
__device__ __align__(1024) __half g_eb[(size_t)NC * 512];      // e_hi
__device__ __align__(1024) float  g_z[(size_t)NROWS * DB];     // fp32 z
__device__ __align__(1024) __half g_Dk[(size_t)NROWS * NC];    // fp16 selection keys
__device__ __align__(1024) uint2  g_sel[(size_t)NROWS * KTOP]; // (w bits, idx)
__device__ float g_enorm[NC];
__device__ float g_usage[NC];
__device__ float g_vq;

// ---------------- helpers -----------------------------------------------------
__device__ __forceinline__ void cp16(void* dst, const void* src) {
    uint32_t d = (uint32_t)__cvta_generic_to_shared(dst);
    asm volatile("cp.async.cg.shared.global [%0], [%1], 16;" :: "r"(d), "l"(src));
}
__device__ __forceinline__ void cp_commit() {
    asm volatile("cp.async.commit_group;" ::: "memory");
}
__device__ __forceinline__ void split2h(float v, __half& hi, __half& lo) {
    hi = __float2half(v);
    lo = __float2half(v - __half2float(hi));
}
__device__ __forceinline__ void mma16816(float* c, const uint32_t* a,
                                         uint32_t b0, uint32_t b1) {
    asm volatile(
        "mma.sync.aligned.m16n8k16.row.col.f32.f16.f16.f32 "
        "{%0,%1,%2,%3}, {%4,%5,%6,%7}, {%8,%9}, {%0,%1,%2,%3};"
        : "+f"(c[0]), "+f"(c[1]), "+f"(c[2]), "+f"(c[3])
        : "r"(a[0]), "r"(a[1]), "r"(a[2]), "r"(a[3]), "r"(b0), "r"(b1));
}
__device__ __forceinline__ void ldsm4(uint32_t* r, uint32_t addr) {
    asm volatile("ldmatrix.sync.aligned.m8n8.x4.shared.b16 {%0,%1,%2,%3}, [%4];"
        : "=r"(r[0]), "=r"(r[1]), "=r"(r[2]), "=r"(r[3]) : "r"(addr));
}
// monotone u16 map of an fp16 bit pattern (order-preserving total order)
__device__ __forceinline__ uint32_t h2key(uint32_t h16) {
    uint32_t neg = h16 >> 15;
    return h16 ^ (0x8000u | (neg * 0x7FFFu));
}
__device__ __forceinline__ uint32_t key2h(uint32_t k16) {
    uint32_t pos = k16 >> 15;
    return k16 ^ (pos ? 0x8000u : 0xFFFFu);
}

// ---------------- pre-kernels: splits + norms ---------------------------------
__global__ void split_slots_kernel(const float* __restrict__ slots) {
    int idx = blockIdx.x * 256 + threadIdx.x;       // < NROWS*D_IN
    int row = idx >> 8, k = idx & 255;
    __half hi, lo;
    split2h(slots[idx], hi, lo);
    __half* dst = g_as + (size_t)row * 512;
    dst[k] = hi;  dst[256 + k] = lo;
}

__global__ void split_w_kernel(const float* __restrict__ W) {
    int idx = blockIdx.x * 256 + threadIdx.x;       // < D_IN*DB
    int k = idx >> 9, n = idx & 511;                // W[k,n] row-major
    __half hi, lo;
    split2h(W[idx], hi, lo);
    __half* dst = g_wb + (size_t)n * 512;
    dst[k] = hi;  dst[256 + k] = lo;
}

__global__ void init_kernel(const float* __restrict__ embed) {
    int w = threadIdx.x >> 5, lane = threadIdx.x & 31;
    int code = blockIdx.x * 8 + w;
    if (code < NC) {
        const float* e = embed + (size_t)code * DB;
        __half* dst = g_eb + (size_t)code * 512;
        float s = 0.f;
        #pragma unroll
        for (int i = lane; i < DB; i += 32) {
            float v = e[i];
            s += v * v;
            dst[i] = __float2half(v);
        }
        #pragma unroll
        for (int o = 16; o; o >>= 1) s += __shfl_down_sync(0xffffffffu, s, o);
        if (lane == 0) g_enorm[code] = s;
    }
    if (blockIdx.x == 0) {
        for (int i = threadIdx.x; i < NC; i += blockDim.x) g_usage[i] = 0.f;
        if (threadIdx.x == 0) g_vq = 0.f;
    }
}

// ---------------- fp16 mma.sync GEMM: C[M,N] = A[M,K'] * B[N,K']^T --------------
// Block 128x256, 8 warps (2m x 4n), warp tile 64x64, K-chunk 32.
// 3-stage cp.async pipeline, one __syncthreads per chunk.
// EPI=1: 3-term fp16 split GEMM (nibble-mapped blocks); +bias; fp32 C + fp16 z_hi.
// EPI=2: linear K; write fp16 key = enorm[col] - 2*acc - 170 (row-term dropped).
#define SM_PITCH 40
#define A_BYTES  (128 * SM_PITCH * 2)
#define B_BYTES  (256 * SM_PITCH * 2)
#define STAGE    (A_BYTES + B_BYTES)
#define NSTAGE   3
#define GEMM_SMEM (NSTAGE * STAGE)       // 92160

template<int KCH, int EPI>
__global__ void __launch_bounds__(256)
tc_gemm(const __half* __restrict__ A, int lda,
        const __half* __restrict__ B, int ldb,
        const float* __restrict__ bias,
        float* __restrict__ C, int ldc,
        __half* __restrict__ Csplit) {
    extern __shared__ __align__(128) char smem[];
    const uint32_t sbase = (uint32_t)__cvta_generic_to_shared(smem);
    const int tid  = threadIdx.x;
    const int wid  = tid >> 5;
    const int lane = tid & 31;
    const int g    = lane >> 2;
    const int t    = lane & 3;
    const int wm   = wid & 1;
    const int wn   = wid >> 1;
    const int row0 = blockIdx.y * 128;
    const int col0 = blockIdx.x * 256;
    const int r8   = lane & 7;
    const int sub  = lane >> 3;

    float acc[4][8][4];
    #pragma unroll
    for (int mi = 0; mi < 4; mi++)
        #pragma unroll
        for (int nj = 0; nj < 8; nj++)
            #pragma unroll
            for (int q = 0; q < 4; q++) acc[mi][nj][q] = 0.f;

    auto do_copy = [&](int c, int s) {
        char* sA = smem + s * STAGE;
        char* sB = sA + A_BYTES;
        int ak, bk;
        if (EPI == 1) {   // 3 term-pairs over [hi|lo] blocks: (0,0),(0,1),(1,0)
            int term = c >> 3, j = c & 7;
            ak = (int)((0x100u >> (term * 4)) & 15u) * 256 + j * 32;
            bk = (int)((0x010u >> (term * 4)) & 15u) * 256 + j * 32;
        } else {
            ak = c * 32; bk = c * 32;
        }
        #pragma unroll
        for (int i = 0; i < 6; i++) {
            int tt = tid + 256 * i;
            if (tt < 512) {
                int r = tt >> 2, kc = tt & 3;
                cp16(sA + r * (SM_PITCH * 2) + kc * 16,
                     A + (size_t)(row0 + r) * lda + ak + kc * 8);
            } else {
                int u = tt - 512;
                int r = u >> 2, kc = u & 3;
                cp16(sB + r * (SM_PITCH * 2) + kc * 16,
                     B + (size_t)(col0 + r) * ldb + bk + kc * 8);
            }
        }
        cp_commit();
    };

    do_copy(0, 0);
    do_copy(1, 1);
    for (int c = 0; c < KCH; c++) {
        const int s = c % NSTAGE;
        if (c + 1 < KCH) {
            asm volatile("cp.async.wait_group 1;" ::: "memory");
        } else {
            asm volatile("cp.async.wait_group 0;" ::: "memory");
        }
        __syncthreads();

        if (c + 2 < KCH) do_copy(c + 2, (c + 2) % NSTAGE);

        const uint32_t sAu = sbase + s * STAGE;
        const uint32_t sBu = sAu + A_BYTES;
        #pragma unroll
        for (int k16 = 0; k16 < 2; k16++) {
            uint32_t af[4][4];
            {
                int arow = wm * 64 + (sub & 1) * 8 + r8;
                int akc  = k16 * 16 + (sub >> 1) * 8;
                #pragma unroll
                for (int mi = 0; mi < 4; mi++)
                    ldsm4(af[mi], sAu + ((arow + mi * 16) * SM_PITCH + akc) * 2);
            }
            uint32_t bf[4][4];
            {
                int bn  = wn * 64 + (sub >> 1) * 8 + r8;
                int bkc = k16 * 16 + (sub & 1) * 8;
                #pragma unroll
                for (int nj2 = 0; nj2 < 4; nj2++)
                    ldsm4(bf[nj2], sBu + ((bn + nj2 * 16) * SM_PITCH + bkc) * 2);
            }
            #pragma unroll
            for (int nj2 = 0; nj2 < 4; nj2++) {
                #pragma unroll
                for (int mi = 0; mi < 4; mi++) {
                    mma16816(acc[mi][2 * nj2],     af[mi], bf[nj2][0], bf[nj2][1]);
                    mma16816(acc[mi][2 * nj2 + 1], af[mi], bf[nj2][2], bf[nj2][3]);
                }
            }
        }
    }

    if (EPI == 2) {
        __half* Ck = (__half*)C;
        float en0[8], en1[8];
        #pragma unroll
        for (int nj = 0; nj < 8; nj++) {
            int col = col0 + wn * 64 + nj * 8 + t * 2;
            en0[nj] = g_enorm[col] - 170.f;
            en1[nj] = g_enorm[col + 1] - 170.f;
        }
        #pragma unroll
        for (int mi = 0; mi < 4; mi++) {
            #pragma unroll
            for (int nj = 0; nj < 8; nj++) {
                const float* cr = acc[mi][nj];
                int row = row0 + wm * 64 + mi * 16 + g;
                int col = col0 + wn * 64 + nj * 8 + t * 2;
                *(__half2*)(Ck + (size_t)row * ldc + col) =
                    __floats2half2_rn(en0[nj] - 2.f * cr[0], en1[nj] - 2.f * cr[1]);
                *(__half2*)(Ck + (size_t)(row + 8) * ldc + col) =
                    __floats2half2_rn(en0[nj] - 2.f * cr[2], en1[nj] - 2.f * cr[3]);
            }
        }
    } else {
        #pragma unroll
        for (int mi = 0; mi < 4; mi++) {
            #pragma unroll
            for (int nj = 0; nj < 8; nj++) {
                const float* cr = acc[mi][nj];
                int row = row0 + wm * 64 + mi * 16 + g;
                int col = col0 + wn * 64 + nj * 8 + t * 2;
                float bx = bias[col], by = bias[col + 1];
                float v0 = cr[0] + bx, v1 = cr[1] + by;
                float v2 = cr[2] + bx, v3 = cr[3] + by;
                *(float2*)(C + (size_t)row * ldc + col)       = make_float2(v0, v1);
                *(float2*)(C + (size_t)(row + 8) * ldc + col) = make_float2(v2, v3);
                *(__half2*)(Csplit + (size_t)row * 512 + col)       = __floats2half2_rn(v0, v1);
                *(__half2*)(Csplit + (size_t)(row + 8) * 512 + col) = __floats2half2_rn(v2, v3);
            }
        }
    }
}

// ---------------- kernel A: select -> exact refine -> rank -> weights ----------
__global__ void __launch_bounds__(256)
select_kernel(const float* __restrict__ embed, float* __restrict__ out) {
    int w = threadIdx.x >> 5, lane = threadIdx.x & 31;
    int r = blockIdx.x * 8 + w;

    const float4* zr4 = (const float4*)(g_z + (size_t)r * DB);
    float4 zreg[4];
    float zn = 0.f;
    #pragma unroll
    for (int i = 0; i < 4; i++) {
        float4 v = zr4[lane + 32 * i];
        zreg[i] = v;
        zn += v.x * v.x + v.y * v.y + v.z * v.z + v.w * v.w;
    }
    #pragma unroll
    for (int o = 16; o; o >>= 1) zn += __shfl_xor_sync(0xffffffffu, zn, o);

    // pass 1: per-lane min via hmin2 tree
    const uint4* Dr = (const uint4*)(g_Dk + (size_t)r * NC);
    uint4 kv[4];
    #pragma unroll
    for (int it = 0; it < 4; it++) kv[it] = Dr[lane + 32 * it];

    __half2 m2 = *reinterpret_cast<__half2*>(&kv[0].x);
    #pragma unroll
    for (int it = 0; it < 4; it++) {
        __half2 a = *reinterpret_cast<__half2*>(&kv[it].x);
        __half2 b = *reinterpret_cast<__half2*>(&kv[it].y);
        __half2 c = *reinterpret_cast<__half2*>(&kv[it].z);
        __half2 d = *reinterpret_cast<__half2*>(&kv[it].w);
        m2 = __hmin2(m2, __hmin2(__hmin2(a, b), __hmin2(c, d)));
    }
    __half mv = __hmin(__low2half(m2), __high2half(m2));
    uint32_t laneKey = (h2key((uint32_t)__half_as_ushort(mv)) << 5) | (uint32_t)lane;

    // threshold T16 = u16-key of 12th smallest lane-min
    uint32_t m = laneKey, T = 0;
    #pragma unroll
    for (int j = 0; j < KSEL; j++) {
        uint32_t best = m;
        #pragma unroll
        for (int o = 16; o; o >>= 1)
            best = min(best, __shfl_xor_sync(0xffffffffu, best, o));
        T = best;
        if (m == best) m = 0xFFFFFFFFu;
    }
    const uint32_t T16 = T >> 5;
    const uint32_t Tfull = (T16 << 10) | 1023u;
    const __half Th = __ushort_as_half((unsigned short)key2h(T16));

    // pass 2: group-filtered collect
    uint32_t td[KSEL];
    #pragma unroll
    for (int j = 0; j < KSEL; j++) td[j] = 0xFFFFFFFFu;

    auto insert = [&](uint32_t key) {
        if (key <= Tfull && key < td[KSEL - 1]) {
            #pragma unroll
            for (int j = KSEL - 1; j >= 0; j--) {
                bool shift = (j > 0) && (td[j - 1] > key);
                if (shift) td[j] = td[j - 1];
                else       { td[j] = key; break; }
            }
        }
    };

    #pragma unroll
    for (int it = 0; it < 4; it++) {
        __half2 a = *reinterpret_cast<__half2*>(&kv[it].x);
        __half2 b = *reinterpret_cast<__half2*>(&kv[it].y);
        __half2 c = *reinterpret_cast<__half2*>(&kv[it].z);
        __half2 d = *reinterpret_cast<__half2*>(&kv[it].w);
        __half2 gm2 = __hmin2(__hmin2(a, b), __hmin2(c, d));
        __half gm = __hmin(__low2half(gm2), __high2half(gm2));
        if (__hle(gm, Th)) {
            uint32_t c0 = (uint32_t)(lane + 32 * it) * 8;
            insert((h2key(kv[it].x & 0xFFFFu) << 10) | (c0 + 0));
            insert((h2key(kv[it].x >> 16)     << 10) | (c0 + 1));
            insert((h2key(kv[it].y & 0xFFFFu) << 10) | (c0 + 2));
            insert((h2key(kv[it].y >> 16)     << 10) | (c0 + 3));
            insert((h2key(kv[it].z & 0xFFFFu) << 10) | (c0 + 4));
            insert((h2key(kv[it].z >> 16)     << 10) | (c0 + 5));
            insert((h2key(kv[it].w & 0xFFFFu) << 10) | (c0 + 6));
            insert((h2key(kv[it].w >> 16)     << 10) | (c0 + 7));
        }
    }

    // warp merge
    int ci[KSEL];
    int pos = 0;
    #pragma unroll
    for (int j = 0; j < KSEL; j++) {
        uint32_t cur = (pos < KSEL) ? td[pos] : 0xFFFFFFFFu;
        uint32_t best = cur;
        #pragma unroll
        for (int o = 16; o; o >>= 1)
            best = min(best, __shfl_xor_sync(0xffffffffu, best, o));
        ci[j] = (int)(best & 1023u);
        if (cur == best) pos++;
    }

    // exact fp32 refine
    float dot[KSEL];
    #pragma unroll
    for (int j = 0; j < KSEL; j++) dot[j] = 0.f;
    #pragma unroll
    for (int i = 0; i < 4; i++) {
        int c4 = lane + 32 * i;
        float4 zv = zreg[i];
        #pragma unroll
        for (int j = 0; j < KSEL; j++) {
            float4 f = ((const float4*)(embed + (size_t)ci[j] * DB))[c4];
            dot[j] += zv.x * f.x + zv.y * f.y + zv.z * f.z + zv.w * f.w;
        }
    }
    #pragma unroll
    for (int o = 16; o; o >>= 1) {
        #pragma unroll
        for (int j = 0; j < KSEL; j++)
            dot[j] += __shfl_xor_sync(0xffffffffu, dot[j], o);
    }
    float xd[KSEL];
    #pragma unroll
    for (int j = 0; j < KSEL; j++) xd[j] = zn + g_enorm[ci[j]] - 2.f * dot[j];

    // rank-based order: lane j (<12) owns candidate j
    float myd = (lane < KSEL) ? xd[lane] : FLT_MAX;
    int   myi = (lane < KSEL) ? ci[lane] : 0x7fffffff;
    int rank = 0;
    #pragma unroll
    for (int j = 0; j < KSEL; j++)
        rank += (xd[j] < myd) || (xd[j] == myd && ci[j] < myi);
    if (lane >= KSEL) rank = 31;

    // distributed softmax over rank<8
    uint32_t m0 = __ballot_sync(0xffffffffu, rank == 0);
    int src0 = __ffs(m0) - 1;
    float v  = sqrtf(fmaxf(myd, 0.f));
    float vmin = __shfl_sync(0xffffffffu, v, src0);
    float wj = (rank < KTOP) ? expf(-(v - vmin) / TEMP) : 0.f;
    float wsum = wj;
    #pragma unroll
    for (int o = 16; o; o >>= 1) wsum += __shfl_xor_sync(0xffffffffu, wsum, o);
    wj /= wsum;

    if (rank < KTOP) {
        g_sel[(size_t)r * KTOP + rank] = make_uint2(__float_as_uint(wj), (uint32_t)myi);
        atomicAdd(&g_usage[myi], wj);
        if (rank == 0) out[(size_t)NROWS * DB + r] = (float)myi;
    }
}

// ---------------- kernel B: q gather + vq --------------------------------------
__global__ void __launch_bounds__(256)
gather_kernel(const float* __restrict__ embed, float* __restrict__ out) {
    int w = threadIdx.x >> 5, lane = threadIdx.x & 31;
    int r = blockIdx.x * 8 + w;

    uint2 p = make_uint2(0, 0);
    if (lane < KTOP) p = g_sel[(size_t)r * KTOP + lane];
    float wv = __uint_as_float(p.x);
    int   iv = (int)p.y;

    float w8[KTOP]; int i8[KTOP];
    #pragma unroll
    for (int j = 0; j < KTOP; j++) {
        w8[j] = __shfl_sync(0xffffffffu, wv, j);
        i8[j] = __shfl_sync(0xffffffffu, iv, j);
    }

    const float4* zr4 = (const float4*)(g_z + (size_t)r * DB);
    float vql = 0.f;
    #pragma unroll
    for (int i = 0; i < 4; i++) {
        int c4 = lane + 32 * i;
        float4 a = make_float4(0.f, 0.f, 0.f, 0.f);
        #pragma unroll
        for (int j = 0; j < KTOP; j++) {
            float4 f = ((const float4*)(embed + (size_t)i8[j] * DB))[c4];
            a.x += w8[j] * f.x; a.y += w8[j] * f.y;
            a.z += w8[j] * f.z; a.w += w8[j] * f.w;
        }
        ((float4*)(out + (size_t)r * DB))[c4] = a;
        float4 zv = zr4[c4];
        float dx = zv.x - a.x, dy = zv.y - a.y;
        float dz = zv.z - a.z, dw = zv.w - a.w;
        vql += dx * dx + dy * dy + dz * dz + dw * dw;
    }
    #pragma unroll
    for (int o = 16; o; o >>= 1) vql += __shfl_down_sync(0xffffffffu, vql, o);
    if (lane == 0) atomicAdd(&g_vq, vql);
}

// ---------------- finalize scalars --------------------------------------------
__global__ void finalize_kernel(float* __restrict__ out) {
    __shared__ float sh[256];
    float s = 0.f;
    for (int c = threadIdx.x; c < NC; c += 256) {
        float u = g_usage[c] * (1.f / (float)NROWS);
        s += u * logf(u + 1e-8f);
    }
    sh[threadIdx.x] = s;
    __syncthreads();
    for (int o = 128; o; o >>= 1) {
        if (threadIdx.x < o) sh[threadIdx.x] += sh[threadIdx.x + o];
        __syncthreads();
    }
    if (threadIdx.x == 0) {
        size_t base = (size_t)NROWS * DB + NROWS;
        out[base + 0] = g_vq * (1.f / (float)((size_t)NROWS * DB));
        out[base + 1] = -sh[0];
    }
}

// ---------------- launch --------------------------------------------------------
extern "C" void kernel_launch(void* const* d_in, const int* in_sizes, int n_in,
                              void* d_out, int out_size) {
    const float* slots = (const float*)d_in[0];
    const float* W     = (const float*)d_in[1];
    const float* bias  = (const float*)d_in[2];
    const float* embed = (const float*)d_in[3];
    float* out = (float*)d_out;

    float* zp = nullptr;
    __half *dkp = nullptr, *asp = nullptr, *wbp = nullptr, *zsp = nullptr, *ebp = nullptr;
    cudaGetSymbolAddress((void**)&zp,  g_z);
    cudaGetSymbolAddress((void**)&dkp, g_Dk);
    cudaGetSymbolAddress((void**)&asp, g_as);
    cudaGetSymbolAddress((void**)&wbp, g_wb);
    cudaGetSymbolAddress((void**)&zsp, g_zs);
    cudaGetSymbolAddress((void**)&ebp, g_eb);

    cudaFuncSetAttribute(tc_gemm<24, 1>,
                         cudaFuncAttributeMaxDynamicSharedMemorySize, GEMM_SMEM);
    cudaFuncSetAttribute(tc_gemm<16, 2>,
                         cudaFuncAttributeMaxDynamicSharedMemorySize, GEMM_SMEM);

    split_slots_kernel<<<(NROWS * D_IN) / 256, 256>>>(slots);
    split_w_kernel<<<(D_IN * DB) / 256, 256>>>(W);
    init_kernel<<<128, 256>>>(embed);

    // z = slots @ W + b : fp16 2-way split, 3 terms, K'=768 -> fp32 z + fp16 z_hi
    tc_gemm<24, 1><<<dim3(2, 128), 256, GEMM_SMEM>>>(
        asp, 512, wbp, 512, bias, zp, 512, zsp);

    // fp16 selection keys = enorm - 2*(z_hi . e_hi) - 170 : K = 512
    tc_gemm<16, 2><<<dim3(4, 128), 256, GEMM_SMEM>>>(
        zsp, 512, ebp, 512, nullptr, (float*)dkp, 1024, nullptr);

    select_kernel<<<NROWS / 8, 256>>>(embed, out);
    gather_kernel<<<NROWS / 8, 256>>>(embed, out);
    finalize_kernel<<<1, 256>>>(out);
}

// round 17
// speedup vs baseline: 1.2898x; 1.0368x over previous
#include <cuda_runtime.h>
#include <cuda_bf16.h>
#include <cuda_fp16.h>
#include <math.h>
#include <float.h>
#include <stdint.h>

// Problem constants (fixed by the dataset)
#define NROWS 16384   // B*K = 256*64
#define D_IN  256
#define DB    512
#define NC    1024
#define KTOP  8
#define KSEL  12      // refine candidates
#define TEMP  0.1f

// ---------------- scratch (static device globals; no allocation) -------------
// fp16 2-way split: products are EXACT in fp32 accum (11+11 mantissa bits < 24).
// GEMM1 (z = slots@W): 3 terms (hi.hi + hi.lo + lo.hi) -> K' = 768
// GEMM2 (keys): single term z_hi . e_hi, K = 512
__device__ __align__(1024) __half g_as[(size_t)NROWS * 512];   // [a_hi|a_lo]
__device__ __align__(1024) __half g_wb[(size_t)DB * 512];      // [w_hi|w_lo]
__device__ __align__(1024) __half g_zs[(size_t)NROWS * 512];   // z_hi
__device__ __align__(1024) __half g_eb[(size_t)NC * 512];      // e_hi
__device__ __align__(1024) float  g_z[(size_t)NROWS * DB];     // fp32 z
__device__ __align__(1024) __half g_Dk[(size_t)NROWS * NC];    // fp16 selection keys
__device__ __align__(1024) uint2  g_sel[(size_t)NROWS * KTOP]; // (w bits, idx)
__device__ float g_enorm[NC];
__device__ float g_usage[NC];
__device__ float g_vq;

// ---------------- helpers -----------------------------------------------------
__device__ __forceinline__ void cp16(void* dst, const void* src) {
    uint32_t d = (uint32_t)__cvta_generic_to_shared(dst);
    asm volatile("cp.async.cg.shared.global [%0], [%1], 16;" :: "r"(d), "l"(src));
}
__device__ __forceinline__ void cp_commit() {
    asm volatile("cp.async.commit_group;" ::: "memory");
}
__device__ __forceinline__ void split2h(float v, __half& hi, __half& lo) {
    hi = __float2half(v);
    lo = __float2half(v - __half2float(hi));
}
__device__ __forceinline__ void mma16816(float* c, const uint32_t* a,
                                         uint32_t b0, uint32_t b1) {
    asm volatile(
        "mma.sync.aligned.m16n8k16.row.col.f32.f16.f16.f32 "
        "{%0,%1,%2,%3}, {%4,%5,%6,%7}, {%8,%9}, {%0,%1,%2,%3};"
        : "+f"(c[0]), "+f"(c[1]), "+f"(c[2]), "+f"(c[3])
        : "r"(a[0]), "r"(a[1]), "r"(a[2]), "r"(a[3]), "r"(b0), "r"(b1));
}
__device__ __forceinline__ void ldsm4(uint32_t* r, uint32_t addr) {
    asm volatile("ldmatrix.sync.aligned.m8n8.x4.shared.b16 {%0,%1,%2,%3}, [%4];"
        : "=r"(r[0]), "=r"(r[1]), "=r"(r[2]), "=r"(r[3]) : "r"(addr));
}
// monotone u16 map of an fp16 bit pattern (order-preserving total order)
__device__ __forceinline__ uint32_t h2key(uint32_t h16) {
    uint32_t neg = h16 >> 15;
    return h16 ^ (0x8000u | (neg * 0x7FFFu));
}
__device__ __forceinline__ uint32_t key2h(uint32_t k16) {
    uint32_t pos = k16 >> 15;
    return k16 ^ (pos ? 0x8000u : 0xFFFFu);
}

// ---------------- pre-kernels: splits + norms ---------------------------------
__global__ void split_slots_kernel(const float* __restrict__ slots) {
    int idx = blockIdx.x * 256 + threadIdx.x;       // < NROWS*D_IN
    int row = idx >> 8, k = idx & 255;
    __half hi, lo;
    split2h(slots[idx], hi, lo);
    __half* dst = g_as + (size_t)row * 512;
    dst[k] = hi;  dst[256 + k] = lo;
}

__global__ void split_w_kernel(const float* __restrict__ W) {
    int idx = blockIdx.x * 256 + threadIdx.x;       // < D_IN*DB
    int k = idx >> 9, n = idx & 511;                // W[k,n] row-major
    __half hi, lo;
    split2h(W[idx], hi, lo);
    __half* dst = g_wb + (size_t)n * 512;
    dst[k] = hi;  dst[256 + k] = lo;
}

__global__ void init_kernel(const float* __restrict__ embed) {
    int w = threadIdx.x >> 5, lane = threadIdx.x & 31;
    int code = blockIdx.x * 8 + w;
    if (code < NC) {
        const float* e = embed + (size_t)code * DB;
        __half* dst = g_eb + (size_t)code * 512;
        float s = 0.f;
        #pragma unroll
        for (int i = lane; i < DB; i += 32) {
            float v = e[i];
            s += v * v;
            dst[i] = __float2half(v);
        }
        #pragma unroll
        for (int o = 16; o; o >>= 1) s += __shfl_down_sync(0xffffffffu, s, o);
        if (lane == 0) g_enorm[code] = s;
    }
    if (blockIdx.x == 0) {
        for (int i = threadIdx.x; i < NC; i += blockDim.x) g_usage[i] = 0.f;
        if (threadIdx.x == 0) g_vq = 0.f;
    }
}

// ---------------- fp16 mma.sync GEMM: C[M,N] = A[M,K'] * B[N,K']^T --------------
// Block 128x256, 8 warps (2m x 4n), warp tile 64x64, K-chunk 32.
// 3-stage cp.async pipeline, one __syncthreads per chunk.
// EPI=1: 3-term fp16 split GEMM (nibble-mapped blocks); +bias; fp32 C + fp16 z_hi.
// EPI=2: linear K; write fp16 key = enorm[col] - 2*acc - 170 (row-term dropped).
#define SM_PITCH 40
#define A_BYTES  (128 * SM_PITCH * 2)
#define B_BYTES  (256 * SM_PITCH * 2)
#define STAGE    (A_BYTES + B_BYTES)
#define NSTAGE   3
#define GEMM_SMEM (NSTAGE * STAGE)       // 92160

template<int KCH, int EPI>
__global__ void __launch_bounds__(256)
tc_gemm(const __half* __restrict__ A, int lda,
        const __half* __restrict__ B, int ldb,
        const float* __restrict__ bias,
        float* __restrict__ C, int ldc,
        __half* __restrict__ Csplit) {
    extern __shared__ __align__(128) char smem[];
    const uint32_t sbase = (uint32_t)__cvta_generic_to_shared(smem);
    const int tid  = threadIdx.x;
    const int wid  = tid >> 5;
    const int lane = tid & 31;
    const int g    = lane >> 2;
    const int t    = lane & 3;
    const int wm   = wid & 1;
    const int wn   = wid >> 1;
    const int row0 = blockIdx.y * 128;
    const int col0 = blockIdx.x * 256;
    const int r8   = lane & 7;
    const int sub  = lane >> 3;

    float acc[4][8][4];
    #pragma unroll
    for (int mi = 0; mi < 4; mi++)
        #pragma unroll
        for (int nj = 0; nj < 8; nj++)
            #pragma unroll
            for (int q = 0; q < 4; q++) acc[mi][nj][q] = 0.f;

    auto do_copy = [&](int c, int s) {
        char* sA = smem + s * STAGE;
        char* sB = sA + A_BYTES;
        int ak, bk;
        if (EPI == 1) {   // 3 term-pairs over [hi|lo] blocks: (0,0),(0,1),(1,0)
            int term = c >> 3, j = c & 7;
            ak = (int)((0x100u >> (term * 4)) & 15u) * 256 + j * 32;
            bk = (int)((0x010u >> (term * 4)) & 15u) * 256 + j * 32;
        } else {
            ak = c * 32; bk = c * 32;
        }
        #pragma unroll
        for (int i = 0; i < 6; i++) {
            int tt = tid + 256 * i;
            if (tt < 512) {
                int r = tt >> 2, kc = tt & 3;
                cp16(sA + r * (SM_PITCH * 2) + kc * 16,
                     A + (size_t)(row0 + r) * lda + ak + kc * 8);
            } else {
                int u = tt - 512;
                int r = u >> 2, kc = u & 3;
                cp16(sB + r * (SM_PITCH * 2) + kc * 16,
                     B + (size_t)(col0 + r) * ldb + bk + kc * 8);
            }
        }
        cp_commit();
    };

    do_copy(0, 0);
    do_copy(1, 1);
    for (int c = 0; c < KCH; c++) {
        const int s = c % NSTAGE;
        if (c + 1 < KCH) {
            asm volatile("cp.async.wait_group 1;" ::: "memory");
        } else {
            asm volatile("cp.async.wait_group 0;" ::: "memory");
        }
        __syncthreads();

        if (c + 2 < KCH) do_copy(c + 2, (c + 2) % NSTAGE);

        const uint32_t sAu = sbase + s * STAGE;
        const uint32_t sBu = sAu + A_BYTES;
        #pragma unroll
        for (int k16 = 0; k16 < 2; k16++) {
            uint32_t af[4][4];
            {
                int arow = wm * 64 + (sub & 1) * 8 + r8;
                int akc  = k16 * 16 + (sub >> 1) * 8;
                #pragma unroll
                for (int mi = 0; mi < 4; mi++)
                    ldsm4(af[mi], sAu + ((arow + mi * 16) * SM_PITCH + akc) * 2);
            }
            uint32_t bf[4][4];
            {
                int bn  = wn * 64 + (sub >> 1) * 8 + r8;
                int bkc = k16 * 16 + (sub & 1) * 8;
                #pragma unroll
                for (int nj2 = 0; nj2 < 4; nj2++)
                    ldsm4(bf[nj2], sBu + ((bn + nj2 * 16) * SM_PITCH + bkc) * 2);
            }
            #pragma unroll
            for (int nj2 = 0; nj2 < 4; nj2++) {
                #pragma unroll
                for (int mi = 0; mi < 4; mi++) {
                    mma16816(acc[mi][2 * nj2],     af[mi], bf[nj2][0], bf[nj2][1]);
                    mma16816(acc[mi][2 * nj2 + 1], af[mi], bf[nj2][2], bf[nj2][3]);
                }
            }
        }
    }

    if (EPI == 2) {
        __half* Ck = (__half*)C;
        float en0[8], en1[8];
        #pragma unroll
        for (int nj = 0; nj < 8; nj++) {
            int col = col0 + wn * 64 + nj * 8 + t * 2;
            en0[nj] = g_enorm[col] - 170.f;
            en1[nj] = g_enorm[col + 1] - 170.f;
        }
        #pragma unroll
        for (int mi = 0; mi < 4; mi++) {
            #pragma unroll
            for (int nj = 0; nj < 8; nj++) {
                const float* cr = acc[mi][nj];
                int row = row0 + wm * 64 + mi * 16 + g;
                int col = col0 + wn * 64 + nj * 8 + t * 2;
                *(__half2*)(Ck + (size_t)row * ldc + col) =
                    __floats2half2_rn(en0[nj] - 2.f * cr[0], en1[nj] - 2.f * cr[1]);
                *(__half2*)(Ck + (size_t)(row + 8) * ldc + col) =
                    __floats2half2_rn(en0[nj] - 2.f * cr[2], en1[nj] - 2.f * cr[3]);
            }
        }
    } else {
        #pragma unroll
        for (int mi = 0; mi < 4; mi++) {
            #pragma unroll
            for (int nj = 0; nj < 8; nj++) {
                const float* cr = acc[mi][nj];
                int row = row0 + wm * 64 + mi * 16 + g;
                int col = col0 + wn * 64 + nj * 8 + t * 2;
                float bx = bias[col], by = bias[col + 1];
                float v0 = cr[0] + bx, v1 = cr[1] + by;
                float v2 = cr[2] + bx, v3 = cr[3] + by;
                *(float2*)(C + (size_t)row * ldc + col)       = make_float2(v0, v1);
                *(float2*)(C + (size_t)(row + 8) * ldc + col) = make_float2(v2, v3);
                *(__half2*)(Csplit + (size_t)row * 512 + col)       = __floats2half2_rn(v0, v1);
                *(__half2*)(Csplit + (size_t)(row + 8) * 512 + col) = __floats2half2_rn(v2, v3);
            }
        }
    }
}

// ---------------- kernel A: select -> exact refine -> rank -> weights ----------
__global__ void __launch_bounds__(256)
select_kernel(const float* __restrict__ embed, float* __restrict__ out) {
    int w = threadIdx.x >> 5, lane = threadIdx.x & 31;
    int r = blockIdx.x * 8 + w;

    const float4* zr4 = (const float4*)(g_z + (size_t)r * DB);
    float4 zreg[4];
    float zn = 0.f;
    #pragma unroll
    for (int i = 0; i < 4; i++) {
        float4 v = zr4[lane + 32 * i];
        zreg[i] = v;
        zn += v.x * v.x + v.y * v.y + v.z * v.z + v.w * v.w;
    }
    #pragma unroll
    for (int o = 16; o; o >>= 1) zn += __shfl_xor_sync(0xffffffffu, zn, o);

    // pass 1: per-lane min via hmin2 tree
    const uint4* Dr = (const uint4*)(g_Dk + (size_t)r * NC);
    uint4 kv[4];
    #pragma unroll
    for (int it = 0; it < 4; it++) kv[it] = Dr[lane + 32 * it];

    __half2 m2 = *reinterpret_cast<__half2*>(&kv[0].x);
    #pragma unroll
    for (int it = 0; it < 4; it++) {
        __half2 a = *reinterpret_cast<__half2*>(&kv[it].x);
        __half2 b = *reinterpret_cast<__half2*>(&kv[it].y);
        __half2 c = *reinterpret_cast<__half2*>(&kv[it].z);
        __half2 d = *reinterpret_cast<__half2*>(&kv[it].w);
        m2 = __hmin2(m2, __hmin2(__hmin2(a, b), __hmin2(c, d)));
    }
    __half mv = __hmin(__low2half(m2), __high2half(m2));
    uint32_t laneKey = (h2key((uint32_t)__half_as_ushort(mv)) << 5) | (uint32_t)lane;

    // threshold T16 = u16-key of 12th smallest lane-min (REDUX.MIN rounds)
    uint32_t m = laneKey, T = 0;
    #pragma unroll
    for (int j = 0; j < KSEL; j++) {
        uint32_t best = __reduce_min_sync(0xffffffffu, m);
        T = best;
        if (m == best) m = 0xFFFFFFFFu;
    }
    const uint32_t T16 = T >> 5;
    const uint32_t Tfull = (T16 << 10) | 1023u;
    const __half Th = __ushort_as_half((unsigned short)key2h(T16));

    // pass 2: group-filtered collect
    uint32_t td[KSEL];
    #pragma unroll
    for (int j = 0; j < KSEL; j++) td[j] = 0xFFFFFFFFu;

    auto insert = [&](uint32_t key) {
        if (key <= Tfull && key < td[KSEL - 1]) {
            #pragma unroll
            for (int j = KSEL - 1; j >= 0; j--) {
                bool shift = (j > 0) && (td[j - 1] > key);
                if (shift) td[j] = td[j - 1];
                else       { td[j] = key; break; }
            }
        }
    };

    #pragma unroll
    for (int it = 0; it < 4; it++) {
        __half2 a = *reinterpret_cast<__half2*>(&kv[it].x);
        __half2 b = *reinterpret_cast<__half2*>(&kv[it].y);
        __half2 c = *reinterpret_cast<__half2*>(&kv[it].z);
        __half2 d = *reinterpret_cast<__half2*>(&kv[it].w);
        __half2 gm2 = __hmin2(__hmin2(a, b), __hmin2(c, d));
        __half gm = __hmin(__low2half(gm2), __high2half(gm2));
        if (__hle(gm, Th)) {
            uint32_t c0 = (uint32_t)(lane + 32 * it) * 8;
            insert((h2key(kv[it].x & 0xFFFFu) << 10) | (c0 + 0));
            insert((h2key(kv[it].x >> 16)     << 10) | (c0 + 1));
            insert((h2key(kv[it].y & 0xFFFFu) << 10) | (c0 + 2));
            insert((h2key(kv[it].y >> 16)     << 10) | (c0 + 3));
            insert((h2key(kv[it].z & 0xFFFFu) << 10) | (c0 + 4));
            insert((h2key(kv[it].z >> 16)     << 10) | (c0 + 5));
            insert((h2key(kv[it].w & 0xFFFFu) << 10) | (c0 + 6));
            insert((h2key(kv[it].w >> 16)     << 10) | (c0 + 7));
        }
    }

    // warp merge: 12 rounds of REDUX.MIN (keys unique via idx bits)
    int ci[KSEL];
    int pos = 0;
    #pragma unroll
    for (int j = 0; j < KSEL; j++) {
        uint32_t cur = (pos < KSEL) ? td[pos] : 0xFFFFFFFFu;
        uint32_t best = __reduce_min_sync(0xffffffffu, cur);
        ci[j] = (int)(best & 1023u);
        if (cur == best) pos++;
    }

    // exact fp32 refine
    float dot[KSEL];
    #pragma unroll
    for (int j = 0; j < KSEL; j++) dot[j] = 0.f;
    #pragma unroll
    for (int i = 0; i < 4; i++) {
        int c4 = lane + 32 * i;
        float4 zv = zreg[i];
        #pragma unroll
        for (int j = 0; j < KSEL; j++) {
            float4 f = ((const float4*)(embed + (size_t)ci[j] * DB))[c4];
            dot[j] += zv.x * f.x + zv.y * f.y + zv.z * f.z + zv.w * f.w;
        }
    }
    #pragma unroll
    for (int o = 16; o; o >>= 1) {
        #pragma unroll
        for (int j = 0; j < KSEL; j++)
            dot[j] += __shfl_xor_sync(0xffffffffu, dot[j], o);
    }
    float xd[KSEL];
    #pragma unroll
    for (int j = 0; j < KSEL; j++) xd[j] = zn + g_enorm[ci[j]] - 2.f * dot[j];

    // rank-based order: lane j (<12) owns candidate j
    float myd = (lane < KSEL) ? xd[lane] : FLT_MAX;
    int   myi = (lane < KSEL) ? ci[lane] : 0x7fffffff;
    int rank = 0;
    #pragma unroll
    for (int j = 0; j < KSEL; j++)
        rank += (xd[j] < myd) || (xd[j] == myd && ci[j] < myi);
    if (lane >= KSEL) rank = 31;

    // distributed softmax over rank<8
    uint32_t m0 = __ballot_sync(0xffffffffu, rank == 0);
    int src0 = __ffs(m0) - 1;
    float v  = sqrtf(fmaxf(myd, 0.f));
    float vmin = __shfl_sync(0xffffffffu, v, src0);
    float wj = (rank < KTOP) ? expf(-(v - vmin) / TEMP) : 0.f;
    float wsum = wj;
    #pragma unroll
    for (int o = 16; o; o >>= 1) wsum += __shfl_xor_sync(0xffffffffu, wsum, o);
    wj /= wsum;

    if (rank < KTOP) {
        g_sel[(size_t)r * KTOP + rank] = make_uint2(__float_as_uint(wj), (uint32_t)myi);
        atomicAdd(&g_usage[myi], wj);
        if (rank == 0) out[(size_t)NROWS * DB + r] = (float)myi;
    }
}

// ---------------- kernel B: q gather + vq --------------------------------------
__global__ void __launch_bounds__(256)
gather_kernel(const float* __restrict__ embed, float* __restrict__ out) {
    int w = threadIdx.x >> 5, lane = threadIdx.x & 31;
    int r = blockIdx.x * 8 + w;

    uint2 p = make_uint2(0, 0);
    if (lane < KTOP) p = g_sel[(size_t)r * KTOP + lane];
    float wv = __uint_as_float(p.x);
    int   iv = (int)p.y;

    float w8[KTOP]; int i8[KTOP];
    #pragma unroll
    for (int j = 0; j < KTOP; j++) {
        w8[j] = __shfl_sync(0xffffffffu, wv, j);
        i8[j] = __shfl_sync(0xffffffffu, iv, j);
    }

    const float4* zr4 = (const float4*)(g_z + (size_t)r * DB);
    float vql = 0.f;
    #pragma unroll
    for (int i = 0; i < 4; i++) {
        int c4 = lane + 32 * i;
        float4 a = make_float4(0.f, 0.f, 0.f, 0.f);
        #pragma unroll
        for (int j = 0; j < KTOP; j++) {
            float4 f = ((const float4*)(embed + (size_t)i8[j] * DB))[c4];
            a.x += w8[j] * f.x; a.y += w8[j] * f.y;
            a.z += w8[j] * f.z; a.w += w8[j] * f.w;
        }
        ((float4*)(out + (size_t)r * DB))[c4] = a;
        float4 zv = zr4[c4];
        float dx = zv.x - a.x, dy = zv.y - a.y;
        float dz = zv.z - a.z, dw = zv.w - a.w;
        vql += dx * dx + dy * dy + dz * dz + dw * dw;
    }
    #pragma unroll
    for (int o = 16; o; o >>= 1) vql += __shfl_down_sync(0xffffffffu, vql, o);
    if (lane == 0) atomicAdd(&g_vq, vql);
}

// ---------------- finalize scalars --------------------------------------------
__global__ void finalize_kernel(float* __restrict__ out) {
    __shared__ float sh[256];
    float s = 0.f;
    for (int c = threadIdx.x; c < NC; c += 256) {
        float u = g_usage[c] * (1.f / (float)NROWS);
        s += u * logf(u + 1e-8f);
    }
    sh[threadIdx.x] = s;
    __syncthreads();
    for (int o = 128; o; o >>= 1) {
        if (threadIdx.x < o) sh[threadIdx.x] += sh[threadIdx.x + o];
        __syncthreads();
    }
    if (threadIdx.x == 0) {
        size_t base = (size_t)NROWS * DB + NROWS;
        out[base + 0] = g_vq * (1.f / (float)((size_t)NROWS * DB));
        out[base + 1] = -sh[0];
    }
}

// ---------------- launch --------------------------------------------------------
extern "C" void kernel_launch(void* const* d_in, const int* in_sizes, int n_in,
                              void* d_out, int out_size) {
    const float* slots = (const float*)d_in[0];
    const float* W     = (const float*)d_in[1];
    const float* bias  = (const float*)d_in[2];
    const float* embed = (const float*)d_in[3];
    float* out = (float*)d_out;

    float* zp = nullptr;
    __half *dkp = nullptr, *asp = nullptr, *wbp = nullptr, *zsp = nullptr, *ebp = nullptr;
    cudaGetSymbolAddress((void**)&zp,  g_z);
    cudaGetSymbolAddress((void**)&dkp, g_Dk);
    cudaGetSymbolAddress((void**)&asp, g_as);
    cudaGetSymbolAddress((void**)&wbp, g_wb);
    cudaGetSymbolAddress((void**)&zsp, g_zs);
    cudaGetSymbolAddress((void**)&ebp, g_eb);

    cudaFuncSetAttribute(tc_gemm<24, 1>,
                         cudaFuncAttributeMaxDynamicSharedMemorySize, GEMM_SMEM);
    cudaFuncSetAttribute(tc_gemm<16, 2>,
                         cudaFuncAttributeMaxDynamicSharedMemorySize, GEMM_SMEM);

    split_slots_kernel<<<(NROWS * D_IN) / 256, 256>>>(slots);
    split_w_kernel<<<(D_IN * DB) / 256, 256>>>(W);
    init_kernel<<<128, 256>>>(embed);

    // z = slots @ W + b : fp16 2-way split, 3 terms, K'=768 -> fp32 z + fp16 z_hi
    tc_gemm<24, 1><<<dim3(2, 128), 256, GEMM_SMEM>>>(
        asp, 512, wbp, 512, bias, zp, 512, zsp);

    // fp16 selection keys = enorm - 2*(z_hi . e_hi) - 170 : K = 512
    tc_gemm<16, 2><<<dim3(4, 128), 256, GEMM_SMEM>>>(
        zsp, 512, ebp, 512, nullptr, (float*)dkp, 1024, nullptr);

    select_kernel<<<NROWS / 8, 256>>>(embed, out);
    gather_kernel<<<NROWS / 8, 256>>>(embed, out);
    finalize_kernel<<<1, 256>>>(out);
}